// round 12
// baseline (speedup 1.0000x reference)
#include <cuda_runtime.h>
#include <cstdint>

#define MDIM 12288
#define CIN 8
#define NPAIR 4
#define COUT 16
#define KTAP 5

#define RPW 7                    // rows per consumer warp
#define NWC 4                    // consumer warps
#define RPB (RPW * NWC)          // 28 rows per CTA
#define NCTHR (NWC * 32)         // 128 consumer threads
#define NTHR (NCTHR + 32)        // +1 producer warp = 160
#define GRID 439                 // ceil(12288/28)

#define SCOLS 128                // columns per ring stage
#define NS 4                     // ring depth
#define NSTG (MDIM / SCOLS)      // 96
#define STAGE_L (RPB * SCOLS * 4)    // 14336 B  (L rows chunk)
#define STAGE_P (SCOLS * CIN * 4)    // 4096 B   (panel chunk, swizzled pair-packed)
#define STAGE_B (STAGE_L + STAGE_P)  // 18432 B

#define SM_FULL  0               // 4 mbarriers (8B each)
#define SM_EMPTY 64
#define SM_RING  128
#define SMEM_TOTAL (SM_RING + NS * STAGE_B)   // 73856 B -> 3 CTAs/SM

#define SWZ(b) ((b) ^ (((b) >> 3) & 0x70))

// Panels in column-major [M][CIN] layout (8 floats contiguous per m).
__device__ __align__(16) float g_pan[KTAP - 1][MDIM * CIN];
__device__ __align__(16) float g_xT[MDIM * CIN];

// ---------- helpers ----------
__device__ __forceinline__ uint32_t smem_u32(const void* p) {
    uint32_t a;
    asm("{ .reg .u64 t; cvta.to.shared.u64 t, %1; cvt.u32.u64 %0, t; }" : "=r"(a) : "l"(p));
    return a;
}
__device__ __forceinline__ unsigned long long pack2(float lo, float hi) {
    unsigned long long r;
    asm("mov.b64 %0, {%1, %2};" : "=l"(r) : "f"(lo), "f"(hi));
    return r;
}
__device__ __forceinline__ void unpack2(unsigned long long v, float& lo, float& hi) {
    asm("mov.b64 {%0, %1}, %2;" : "=f"(lo), "=f"(hi) : "l"(v));
}
__device__ __forceinline__ void fma2(unsigned long long& acc,
                                     unsigned long long a, unsigned long long b) {
    asm("fma.rn.f32x2 %0, %1, %2, %0;" : "+l"(acc) : "l"(a), "l"(b));
}
__device__ __forceinline__ void cp16(uint32_t dst, const void* src) {
    asm volatile("cp.async.cg.shared.global [%0], [%1], 16;" :: "r"(dst), "l"(src) : "memory");
}
__device__ __forceinline__ void cp_commit() {
    asm volatile("cp.async.commit_group;" ::: "memory");
}
template <int N>
__device__ __forceinline__ void cp_wait() {
    asm volatile("cp.async.wait_group %0;" :: "n"(N) : "memory");
}
__device__ __forceinline__ void mbar_init(uint32_t a, uint32_t cnt) {
    asm volatile("mbarrier.init.shared.b64 [%0], %1;" :: "r"(a), "r"(cnt) : "memory");
}
__device__ __forceinline__ void mbar_arrive(uint32_t a) {
    asm volatile("mbarrier.arrive.release.cta.shared::cta.b64 _, [%0];" :: "r"(a) : "memory");
}
__device__ __forceinline__ void mbar_wait_acq(uint32_t a, uint32_t ph) {
    asm volatile(
        "{\n\t.reg .pred P;\n\t"
        "WL%=:\n\t"
        "mbarrier.try_wait.parity.acquire.cta.shared::cta.b64 P, [%0], %1, 0x989680;\n\t"
        "@P bra.uni WD%=;\n\t"
        "bra.uni WL%=;\n\t"
        "WD%=:\n\t}"
        :: "r"(a), "r"(ph) : "memory");
}

// xT[m*8 + i] = x[i*M + m]
__global__ __launch_bounds__(256)
void transpose_kernel(const float* __restrict__ x, float* __restrict__ xT) {
    const int m = blockIdx.x * blockDim.x + threadIdx.x;
    if (m >= MDIM) return;
    float v[CIN];
#pragma unroll
    for (int i = 0; i < CIN; ++i) v[i] = x[(size_t)i * MDIM + m];
    float4* dst = reinterpret_cast<float4*>(xT + (size_t)m * CIN);
    dst[0] = make_float4(v[0], v[1], v[2], v[3]);
    dst[1] = make_float4(v[4], v[5], v[6], v[7]);
}

// nxt[m][i] = sum_j L[m][j] * cur[j][i]   (cur, nxt column-major [M][CIN])
// dir: serpentine column order across launches (L2 residue reuse).
// fin: if nonzero, fused mix epilogue writes y directly instead of storing p4.
__global__ __launch_bounds__(NTHR, 3)
void step_kernel(const float* __restrict__ L,
                 const float* __restrict__ cur,
                 float* __restrict__ nxt,
                 int dir, int fin,
                 const float* __restrict__ theta,
                 const float* __restrict__ bias,
                 float* __restrict__ out) {
    extern __shared__ __align__(128) unsigned char dsm[];
    const uint32_t smb = smem_u32(dsm);
    const int tid  = threadIdx.x;
    const int lane = tid & 31;
    const int w    = tid >> 5;
    const int m0   = blockIdx.x * RPB;

    if (tid == 0) {
#pragma unroll
        for (int s = 0; s < NS; ++s) {
            mbar_init(smb + SM_FULL  + 8 * s, 32);   // 32 producer-lane arrivals
            mbar_init(smb + SM_EMPTY + 8 * s, NWC);  // 1 arrive per consumer warp
        }
    }
    __syncthreads();

    if (w == NWC) {
        // ================= producer warp =================
        const unsigned char* curb = reinterpret_cast<const unsigned char*>(cur);
        int eph = 1;                                  // fresh-empty passes immediately
        for (int u = 0; u < NSTG; ++u) {
            const int t    = dir ? (NSTG - 1 - u) : u;   // data stage
            const int slot = u & (NS - 1);               // ring slot
            mbar_wait_acq(smb + SM_EMPTY + 8 * slot, (uint32_t)eph);
            const uint32_t dst0 = smb + SM_RING + slot * STAGE_B;
            const int jb = t * SCOLS;
            // L rows chunk: 28 rows x 512 B (lane covers 16 B of each row)
#pragma unroll
            for (int r = 0; r < RPB; ++r) {
                int mr = m0 + r; if (mr > MDIM - 1) mr = MDIM - 1;   // pad-row clamp
                cp16(dst0 + r * (SCOLS * 4) + lane * 16,
                     L + (size_t)mr * MDIM + jb + lane * 4);
            }
            // panel chunk: 128 cols x 32 B, contiguous src, swizzled dst
#pragma unroll
            for (int q = 0; q < 8; ++q) {
                const uint32_t off = (uint32_t)(lane * 16 + q * 512);
                cp16(dst0 + STAGE_L + SWZ(off),
                     curb + (size_t)jb * 32 + off);
            }
            cp_commit();
            if (u >= 2) {                             // group u-2 retired -> publish
                cp_wait<2>();
                mbar_arrive(smb + SM_FULL + 8 * ((u - 2) & (NS - 1)));
            }
            if (slot == NS - 1) eph ^= 1;
        }
        cp_wait<1>();
        mbar_arrive(smb + SM_FULL + 8 * ((NSTG - 2) & (NS - 1)));
        cp_wait<0>();
        mbar_arrive(smb + SM_FULL + 8 * ((NSTG - 1) & (NS - 1)));
        return;
    }

    // ================= consumer warps =================
    const int r0 = w * RPW;

    unsigned long long acc[RPW][NPAIR];
#pragma unroll
    for (int r = 0; r < RPW; ++r)
#pragma unroll
        for (int p = 0; p < NPAIR; ++p) acc[r][p] = 0ull;

    int fph = 0;
    for (int u = 0; u < NSTG; ++u) {
        const int slot = u & (NS - 1);
        mbar_wait_acq(smb + SM_FULL + 8 * slot, (uint32_t)fph);

        const unsigned char* lb = dsm + SM_RING + slot * STAGE_B;
        float4 a[RPW];
#pragma unroll
        for (int r = 0; r < RPW; ++r)
            a[r] = *reinterpret_cast<const float4*>(
                       lb + (r0 + r) * (SCOLS * 4) + lane * 16);

        const unsigned char* pbp = lb + STAGE_L;
#pragma unroll
        for (int jj = 0; jj < 4; ++jj) {
            const int jl = 4 * lane + jj;              // stage-local column
            ulonglong2 q0 = *reinterpret_cast<const ulonglong2*>(pbp + SWZ(jl * 32));
            ulonglong2 q1 = *reinterpret_cast<const ulonglong2*>(pbp + SWZ(jl * 32 + 16));
#pragma unroll
            for (int r = 0; r < RPW; ++r) {
                float av = (jj == 0) ? a[r].x : (jj == 1) ? a[r].y
                         : (jj == 2) ? a[r].z : a[r].w;
                unsigned long long aa = pack2(av, av);
                fma2(acc[r][0], aa, q0.x);
                fma2(acc[r][1], aa, q0.y);
                fma2(acc[r][2], aa, q1.x);
                fma2(acc[r][3], aa, q1.y);
            }
        }

        if (lane == 0) mbar_arrive(smb + SM_EMPTY + 8 * slot);
        if (slot == NS - 1) fph ^= 1;
    }

    if (!fin) {
        // Intermediate step: reduce to lane 0, store p_{k} (column-major).
#pragma unroll
        for (int r = 0; r < RPW; ++r) {
            const int m = m0 + r0 + r;
            float ov[CIN];
#pragma unroll
            for (int p = 0; p < NPAIR; ++p) {
                float v0, v1;
                unpack2(acc[r][p], v0, v1);
#pragma unroll
                for (int d = 16; d > 0; d >>= 1) {
                    v0 += __shfl_down_sync(0xffffffffu, v0, d);
                    v1 += __shfl_down_sync(0xffffffffu, v1, d);
                }
                ov[2 * p] = v0; ov[2 * p + 1] = v1;
            }
            if (lane == 0 && m < MDIM) {
                float4* dst = reinterpret_cast<float4*>(nxt + (size_t)m * CIN);
                dst[0] = make_float4(ov[0], ov[1], ov[2], ov[3]);
                dst[1] = make_float4(ov[4], ov[5], ov[6], ov[7]);
            }
        }
    } else {
        // Final step: butterfly-reduce (all lanes hold p4), fused mix epilogue.
#pragma unroll
        for (int r = 0; r < RPW; ++r) {
            const int m = m0 + r0 + r;
            float pv[CIN];
#pragma unroll
            for (int p = 0; p < NPAIR; ++p) {
                float v0, v1;
                unpack2(acc[r][p], v0, v1);
#pragma unroll
                for (int d = 16; d > 0; d >>= 1) {
                    v0 += __shfl_xor_sync(0xffffffffu, v0, d);
                    v1 += __shfl_xor_sync(0xffffffffu, v1, d);
                }
                pv[2 * p] = v0; pv[2 * p + 1] = v1;
            }
            if (m >= MDIM) continue;

            // p0..p3 for this m (32B broadcast loads; identical across lanes)
            float pk[4][CIN];
            {
                const float4* s0 = reinterpret_cast<const float4*>(g_xT + (size_t)m * CIN);
                float4 lo = s0[0], hi = s0[1];
                pk[0][0]=lo.x; pk[0][1]=lo.y; pk[0][2]=lo.z; pk[0][3]=lo.w;
                pk[0][4]=hi.x; pk[0][5]=hi.y; pk[0][6]=hi.z; pk[0][7]=hi.w;
            }
#pragma unroll
            for (int k = 1; k < 4; ++k) {
                const float4* sk = reinterpret_cast<const float4*>(
                                       &g_pan[k - 1][(size_t)m * CIN]);
                float4 lo = sk[0], hi = sk[1];
                pk[k][0]=lo.x; pk[k][1]=lo.y; pk[k][2]=lo.z; pk[k][3]=lo.w;
                pk[k][4]=hi.x; pk[k][5]=hi.y; pk[k][6]=hi.z; pk[k][7]=hi.w;
            }

            const int o = lane;
            if (o < COUT) {
                float s = bias[o];
#pragma unroll
                for (int i = 0; i < CIN; ++i) {
                    const float* th = theta + (o * CIN + i) * KTAP;
                    s += th[0] * pk[0][i];
                    s += th[1] * pk[1][i];
                    s += th[2] * pk[2][i];
                    s += th[3] * pk[3][i];
                    s += th[4] * pv[i];
                }
                out[(size_t)o * MDIM + m] = s;
            }
        }
    }
}

extern "C" void kernel_launch(void* const* d_in, const int* in_sizes, int n_in,
                              void* d_out, int out_size) {
    const float* L     = (const float*)d_in[0];
    const float* x     = (const float*)d_in[1];
    const float* theta = (const float*)d_in[2];
    const float* bias  = (const float*)d_in[3];
    float* out = (float*)d_out;

    cudaFuncSetAttribute(step_kernel,
                         cudaFuncAttributeMaxDynamicSharedMemorySize, SMEM_TOTAL);

    float* pan = nullptr;
    cudaGetSymbolAddress((void**)&pan, g_pan);
    float* xT = nullptr;
    cudaGetSymbolAddress((void**)&xT, g_xT);

    const size_t PSZ = (size_t)MDIM * CIN;

    transpose_kernel<<<(MDIM + 255) / 256, 256>>>(x, xT);
    // Serpentine direction: each step starts where the previous one ended
    // (including replay wrap: step 4 ends at low columns, step 1 starts there).
    step_kernel<<<GRID, NTHR, SMEM_TOTAL>>>(L, xT,            pan + 0 * PSZ, 0, 0,
                                            theta, bias, out);
    step_kernel<<<GRID, NTHR, SMEM_TOTAL>>>(L, pan + 0 * PSZ, pan + 1 * PSZ, 1, 0,
                                            theta, bias, out);
    step_kernel<<<GRID, NTHR, SMEM_TOTAL>>>(L, pan + 1 * PSZ, pan + 2 * PSZ, 0, 0,
                                            theta, bias, out);
    // Final step: fused mix epilogue (p4 never hits global memory).
    step_kernel<<<GRID, NTHR, SMEM_TOTAL>>>(L, pan + 2 * PSZ, pan + 3 * PSZ, 1, 1,
                                            theta, bias, out);
}